// round 4
// baseline (speedup 1.0000x reference)
#include <cuda_runtime.h>
#include <math.h>

#define HNUM 512
#define WNUM 512
#define NIMG 12
#define NPIX (NIMG*HNUM*WNUM)
#define WSTRIDE 176

typedef unsigned long long ull;

// ---- scratch (static device memory) ----
__device__ float  d_diff[NPIX];
__device__ ull    d_AB[(size_t)6*NPIX];   // per-sigma interleaved {A=G*d, B=U*d} along W
__device__ float  d_S[(size_t)6*NPIX];    // per-sigma box*d along W (prefix sums)
__device__ float  d_gw[6*WSTRIDE];
__device__ float  d_uw[6*WSTRIDE];
__device__ float  d_c[6];
__device__ double d_accv[64];

__device__ __forceinline__ int refl(int t){
    int r = t < 0 ? -t : t;
    return r >= HNUM ? (2*HNUM - 2 - r) : r;
}
__device__ __forceinline__ ull pk(float x, float y){
    ull r; asm("mov.b64 %0,{%1,%2};" : "=l"(r) : "f"(x), "f"(y)); return r;
}
__device__ __forceinline__ void upk(ull v, float& x, float& y){
    asm("mov.b64 {%0,%1},%2;" : "=f"(x), "=f"(y) : "l"(v));
}
__device__ __forceinline__ void fma2(ull& d, ull a, ull b){
    asm("fma.rn.f32x2 %0,%1,%2,%0;" : "+l"(d) : "l"(a), "l"(b));
}
__device__ __forceinline__ void add2(ull& d, ull a){
    asm("add.rn.f32x2 %0,%0,%1;" : "+l"(d) : "l"(a));
}

// ---- init ----
__global__ void init_kernel(){
    const float sig[6] = {0.6f, 1.2f, 2.4f, 4.8f, 9.6f, 19.2f};
    const int   ks [6] = {5, 11, 21, 39, 77, 155};
    if (threadIdx.x < 64) d_accv[threadIdx.x] = 0.0;
    for (int s = 0; s < 6; ++s){
        int K = ks[s];
        float ss = sig[s]*sig[s];
        float sn = 0.3989422804014327f / ss;
        int half = K/2;
        for (int j = threadIdx.x; j < WSTRIDE; j += blockDim.x){
            float g = 0.f, u = 0.f;
            if (j < K){
                float t  = (float)(j - half);
                float t2 = t*t;
                float e  = expf(-t2 / (2.f*ss));
                g = e * sn;
                u = (t2 - ss) * e * sn;
            }
            d_gw[s*WSTRIDE + j] = g;
            d_uw[s*WSTRIDE + j] = u;
        }
    }
    __syncthreads();
    if (threadIdx.x == 0){
        for (int s = 0; s < 6; ++s){
            int K = ks[s];
            double sg = 0.0, su = 0.0;
            for (int j = 0; j < K; ++j){
                sg += (double)d_gw[s*WSTRIDE + j];
                su += (double)d_uw[s*WSTRIDE + j];
            }
            d_c[s] = (float)(2.0 * sg * su / ((double)K * (double)K));
        }
    }
}

// ---- fused diff + per-row prefix + box-along-W for all sigmas ----
__global__ void __launch_bounds__(256) diff_prefix_kernel(
    const float* __restrict__ in, const float* __restrict__ tg)
{
    __shared__ float dr[512];
    __shared__ float q[667];
    __shared__ float wsum[8];

    const int row = blockIdx.x, img = blockIdx.y;
    const size_t base = ((size_t)img*HNUM + row)*WNUM;
    const int tid = threadIdx.x;

    for (int x = tid; x < 512; x += 256){
        float d = in[base+x] - tg[base+x];
        dr[x] = d;
        d_diff[base+x] = d;
    }
    __syncthreads();

    const int i0 = tid*3;
    float v0 = (i0   < 666) ? dr[refl(i0-77)] : 0.f;
    float v1 = (i0+1 < 666) ? dr[refl(i0-76)] : 0.f;
    float v2 = (i0+2 < 666) ? dr[refl(i0-75)] : 0.f;
    float s01 = v0 + v1;
    float tot = s01 + v2;

    float inc = tot;
#pragma unroll
    for (int off = 1; off < 32; off <<= 1){
        float n = __shfl_up_sync(0xffffffffu, inc, off);
        if ((tid & 31) >= off) inc += n;
    }
    if ((tid & 31) == 31) wsum[tid >> 5] = inc;
    __syncthreads();
    if (tid == 0){
        float a = 0.f;
#pragma unroll
        for (int i = 0; i < 8; ++i){ float t = wsum[i]; wsum[i] = a; a += t; }
    }
    __syncthreads();
    float ex = inc - tot + wsum[tid >> 5];
    if (i0   <= 666) q[i0]   = ex;
    if (i0+1 <= 666) q[i0+1] = ex + v0;
    if (i0+2 <= 666) q[i0+2] = ex + s01;
    __syncthreads();

    const int KS[6] = {5, 11, 21, 39, 77, 155};
#pragma unroll
    for (int s = 0; s < 6; ++s){
        int K = KS[s], P = K >> 1;
        for (int x = tid; x < 512; x += 256){
            int lo = x + 77 - P;
            d_S[(size_t)s*NPIX + base + x] = q[lo + K] - q[lo];
        }
    }
}

// ---- hpass: 2 rows x 512 cols per block; thread = 4 cols x 2 rows (f32x2 = row pair)
template<int K>
__device__ __forceinline__ void hpass_core(int s, int img, char* smraw)
{
    constexpr int P   = K/2;
    constexpr int SH  = ((K + 6)/4)*4;        // >= K+3, mult 4
    constexpr int TS  = 508 + SH;
    constexpr int TSP = (TS + TS/8 + 3) & ~1;
    ull* tile = (ull*)smraw;
    ulonglong2* wgu = (ulonglong2*)(smraw + (size_t)TSP*8);

    const int tx = threadIdx.x;
    const int r0 = blockIdx.x*2;
    const size_t base = ((size_t)img*HNUM + r0)*WNUM;
    const float* src = d_diff + base;
    const float* gwp = d_gw + s*WSTRIDE;
    const float* uwp = d_uw + s*WSTRIDE;

    for (int u = tx; u < TS; u += 128){
        int c = refl(u - P);
        tile[u + (u>>3)] = pk(src[c], src[c+WNUM]);
    }
    for (int t = tx; t < SH; t += 128){
        float g = gwp[t], u_ = uwp[t];
        wgu[t] = make_ulonglong2(pk(g,g), pk(u_,u_));
    }
    __syncthreads();

    ull aG[4], aU[4], wgg[4], wuu[4];
#pragma unroll
    for (int r = 0; r < 4; ++r){ aG[r]=0; aU[r]=0; wgg[r]=0; wuu[r]=0; }

    const int w0 = tx*4;
    for (int t0 = 0; t0 < SH; t0 += 4){
#pragma unroll
        for (int j = 0; j < 4; ++j){
            int t = t0 + j;
            ulonglong2 w = wgu[t];
            wgg[j] = w.x; wuu[j] = w.y;
            int u = w0 + t;
            ull v = tile[u + (u>>3)];
#pragma unroll
            for (int r = 0; r < 4; ++r){
                const int sl = (j - r) & 3;
                fma2(aG[r], wgg[sl], v);
                fma2(aU[r], wuu[sl], v);
            }
        }
    }

    float A0[4], A1[4], B0[4], B1[4];
#pragma unroll
    for (int r = 0; r < 4; ++r){
        upk(aG[r], A0[r], A1[r]);
        upk(aU[r], B0[r], B1[r]);
    }
    ull* dst = d_AB + (size_t)s*NPIX + base + w0;
    *(ulonglong2*)(dst)        = make_ulonglong2(pk(A0[0],B0[0]), pk(A0[1],B0[1]));
    *(ulonglong2*)(dst+2)      = make_ulonglong2(pk(A0[2],B0[2]), pk(A0[3],B0[3]));
    *(ulonglong2*)(dst+WNUM)   = make_ulonglong2(pk(A1[0],B1[0]), pk(A1[1],B1[1]));
    *(ulonglong2*)(dst+WNUM+2) = make_ulonglong2(pk(A1[2],B1[2]), pk(A1[3],B1[3]));
}

__global__ void __launch_bounds__(128) hpass_all()
{
    extern __shared__ char smh[];
    int z = blockIdx.z; int so = z/12; int img = z - so*12;
    switch (so){
        case 0: hpass_core<155>(5, img, smh); break;
        case 1: hpass_core<77 >(4, img, smh); break;
        case 2: hpass_core<39 >(3, img, smh); break;
        case 3: hpass_core<21 >(2, img, smh); break;
        case 4: hpass_core<11 >(1, img, smh); break;
        default:hpass_core<5  >(0, img, smh); break;
    }
}

// ---- vpass: 16 cols x 64 rows per block; thread = 2 cols x 4 rows
template<int K>
__device__ __forceinline__ void vpass_core(int s, int img, char* smraw, float wloss)
{
    constexpr int P  = K/2;
    constexpr int SV = ((K + 6)/4)*4;          // >= K+3, mult 4
    constexpr int TR = 60 + SV;
    ull*   tile = (ull*)smraw;
    ull*   wab  = (ull*)(smraw + (size_t)TR*16*8);
    float* wred = (float*)(smraw + (size_t)TR*16*8 + (size_t)SV*8);

    const int tid = threadIdx.x;
    const int tx = tid & 7, ty = tid >> 3;
    const int rb = ty*4;
    const int col0 = blockIdx.x*16;
    const int h0   = blockIdx.y*64;
    const size_t ibase = (size_t)img*(HNUM*WNUM);
    const ull*   AB = d_AB + (size_t)s*NPIX + ibase;
    const float* Sp = d_S  + (size_t)s*NPIX + ibase;

    const float* uwp = d_uw + s*WSTRIDE;
    const float* gwp = d_gw + s*WSTRIDE;
    for (int t = tid; t < SV; t += 128)
        wab[t] = pk(uwp[t], gwp[t]);
    for (int i = tid; i < TR*16; i += 128){
        int r = i >> 4, cc = i & 15;
        tile[i] = AB[(size_t)refl(h0 + r - P)*WNUM + (col0 + cc)];
    }
    __syncthreads();

    ull accA[4], accB[4], w2[4];
#pragma unroll
    for (int r = 0; r < 4; ++r){ accA[r]=0; accB[r]=0; w2[r]=0; }

    for (int t0 = 0; t0 < SV; t0 += 4){
#pragma unroll
        for (int j = 0; j < 4; ++j){
            int t = t0 + j;
            w2[j] = wab[t];
            ulonglong2 v = *(const ulonglong2*)&tile[(rb + t)*16 + 2*tx];
#pragma unroll
            for (int r = 0; r < 4; ++r){
                const int sl = (j - r) & 3;
                fma2(accA[r], w2[sl], v.x);
                fma2(accB[r], w2[sl], v.y);
            }
        }
    }
    __syncthreads();

    // Phase 2: sliding box over S (tile reused as [TR][8] packed col-pairs)
    ull* tileS = tile;
    for (int i = tid; i < TR*8; i += 128){
        int r = i >> 3, cc = i & 7;
        tileS[i] = *(const ull*)&Sp[(size_t)refl(h0 + r - P)*WNUM + (col0 + 2*cc)];
    }
    __syncthreads();

    ull sbox = 0;
#pragma unroll 8
    for (int t = 0; t < K; ++t) add2(sbox, tileS[(rb + t)*8 + tx]);

    const float cn = -d_c[s];
    const ull NEG1 = pk(-1.f, -1.f);
    float ls = 0.f;
#pragma unroll
    for (int r = 0; r < 4; ++r){
        if (r){
            add2(sbox, tileS[(rb + r - 1 + K)*8 + tx]);
            fma2(sbox, tileS[(rb + r - 1)*8 + tx], NEG1);
        }
        float pA,qA,pB,qB,s0,s1;
        upk(accA[r], pA, qA);
        upk(accB[r], pB, qB);
        upk(sbox, s0, s1);
        float o0 = fmaf(cn, s0, pA + qA);
        float o1 = fmaf(cn, s1, pB + qB);
        ls += o0*o0 + o1*o1;
    }
#pragma unroll
    for (int off = 16; off; off >>= 1) ls += __shfl_down_sync(0xffffffffu, ls, off);
    if ((tid & 31) == 0) wred[tid >> 5] = ls;
    __syncthreads();
    if (tid == 0){
        float tot = wred[0] + wred[1] + wred[2] + wred[3];
        int slot = (blockIdx.x + blockIdx.y*32 + blockIdx.z*7) & 63;
        atomicAdd(&d_accv[slot], (double)tot * (double)wloss);
    }
}

__global__ void __launch_bounds__(128) vpass_all()
{
    extern __shared__ char smv[];
    int z = blockIdx.z; int so = z/12; int img = z - so*12;
    switch (so){
        case 0: vpass_core<155>(5, img, smv, 10.f);  break;
        case 1: vpass_core<77 >(4, img, smv, 10.f);  break;
        case 2: vpass_core<39 >(3, img, smv, 20.f);  break;
        case 3: vpass_core<21 >(2, img, smv, 400.f); break;
        case 4: vpass_core<11 >(1, img, smv, 500.f); break;
        default:vpass_core<5  >(0, img, smv, 600.f); break;
    }
}

// ---- finalize ----
__global__ void final_kernel(float* out){
    double t = 0.0;
#pragma unroll
    for (int i = 0; i < 64; ++i) t += d_accv[i];
    out[0] = (float)(t * (1.0 / (double)NPIX));
}

extern "C" void kernel_launch(void* const* d_in, const int* in_sizes, int n_in,
                              void* d_out, int out_size)
{
    const float* input  = (const float*)d_in[0];
    const float* target = (const float*)d_in[1];
    float* out = (float*)d_out;

    // dynamic smem (max over branches = K=155)
    // hpass: TS=668, TSP=(668+83+3)&~1=754 -> 754*8 + 160*16 = 8592
    const int HS = 8608;
    // vpass: SV=160, TR=220 -> 220*16*8 + 160*8 + 16 = 29456
    const int VS = 29472;

    init_kernel<<<1, 256>>>();
    diff_prefix_kernel<<<dim3(512, NIMG), 256>>>(input, target);
    hpass_all<<<dim3(256, 1, 72), 128, HS>>>();
    vpass_all<<<dim3(32, 8, 72), 128, VS>>>();
    final_kernel<<<1, 1>>>(out);
}

// round 5
// speedup vs baseline: 1.2270x; 1.2270x over previous
#include <cuda_runtime.h>
#include <math.h>

#define HNUM 512
#define WNUM 512
#define NIMG 12
#define NPIX (NIMG*HNUM*WNUM)
#define WSTRIDE 176

typedef unsigned long long ull;

// ---- scratch (static device memory) ----
__device__ float  d_diff[NPIX];
__device__ float  d_A[(size_t)6*NPIX];    // per-sigma G*diff along W
__device__ float  d_B[(size_t)6*NPIX];    // per-sigma U*diff along W
__device__ float  d_S[(size_t)6*NPIX];    // per-sigma box*diff along W (prefix)
__device__ float  d_gw[6*WSTRIDE];
__device__ float  d_uw[6*WSTRIDE];
__device__ float  d_c[6];
__device__ double d_accv[64];

__device__ __forceinline__ int refl(int t){
    int r = t < 0 ? -t : t;
    return r >= HNUM ? (2*HNUM - 2 - r) : r;
}
__device__ __forceinline__ ull pk(float x, float y){
    ull r; asm("mov.b64 %0,{%1,%2};" : "=l"(r) : "f"(x), "f"(y)); return r;
}
__device__ __forceinline__ void upk(ull v, float& x, float& y){
    asm("mov.b64 {%0,%1},%2;" : "=f"(x), "=f"(y) : "l"(v));
}
__device__ __forceinline__ void fma2(ull& d, ull a, ull b){
    asm("fma.rn.f32x2 %0,%1,%2,%0;" : "+l"(d) : "l"(a), "l"(b));
}
__device__ __forceinline__ void add2(ull& d, ull a){
    asm("add.rn.f32x2 %0,%0,%1;" : "+l"(d) : "l"(a));
}

// ---- init ----
__global__ void init_kernel(){
    const float sig[6] = {0.6f, 1.2f, 2.4f, 4.8f, 9.6f, 19.2f};
    const int   ks [6] = {5, 11, 21, 39, 77, 155};
    if (threadIdx.x < 64) d_accv[threadIdx.x] = 0.0;
    for (int s = 0; s < 6; ++s){
        int K = ks[s];
        float ss = sig[s]*sig[s];
        float sn = 0.3989422804014327f / ss;
        int half = K/2;
        for (int j = threadIdx.x; j < WSTRIDE; j += blockDim.x){
            float g = 0.f, u = 0.f;
            if (j < K){
                float t  = (float)(j - half);
                float t2 = t*t;
                float e  = expf(-t2 / (2.f*ss));
                g = e * sn;
                u = (t2 - ss) * e * sn;
            }
            d_gw[s*WSTRIDE + j] = g;
            d_uw[s*WSTRIDE + j] = u;
        }
    }
    __syncthreads();
    if (threadIdx.x == 0){
        for (int s = 0; s < 6; ++s){
            int K = ks[s];
            double sg = 0.0, su = 0.0;
            for (int j = 0; j < K; ++j){
                sg += (double)d_gw[s*WSTRIDE + j];
                su += (double)d_uw[s*WSTRIDE + j];
            }
            d_c[s] = (float)(2.0 * sg * su / ((double)K * (double)K));
        }
    }
}

// ---- fused diff + per-row prefix + box-along-W for all sigmas ----
__global__ void __launch_bounds__(256) diff_prefix_kernel(
    const float* __restrict__ in, const float* __restrict__ tg)
{
    __shared__ float dr[512];
    __shared__ float q[667];
    __shared__ float wsum[8];

    const int row = blockIdx.x, img = blockIdx.y;
    const size_t base = ((size_t)img*HNUM + row)*WNUM;
    const int tid = threadIdx.x;

    for (int x = tid; x < 512; x += 256){
        float d = in[base+x] - tg[base+x];
        dr[x] = d;
        d_diff[base+x] = d;
    }
    __syncthreads();

    const int i0 = tid*3;
    float v0 = (i0   < 666) ? dr[refl(i0-77)] : 0.f;
    float v1 = (i0+1 < 666) ? dr[refl(i0-76)] : 0.f;
    float v2 = (i0+2 < 666) ? dr[refl(i0-75)] : 0.f;
    float s01 = v0 + v1;
    float tot = s01 + v2;

    float inc = tot;
#pragma unroll
    for (int off = 1; off < 32; off <<= 1){
        float n = __shfl_up_sync(0xffffffffu, inc, off);
        if ((tid & 31) >= off) inc += n;
    }
    if ((tid & 31) == 31) wsum[tid >> 5] = inc;
    __syncthreads();
    if (tid == 0){
        float a = 0.f;
#pragma unroll
        for (int i = 0; i < 8; ++i){ float t = wsum[i]; wsum[i] = a; a += t; }
    }
    __syncthreads();
    float ex = inc - tot + wsum[tid >> 5];
    if (i0   <= 666) q[i0]   = ex;
    if (i0+1 <= 666) q[i0+1] = ex + v0;
    if (i0+2 <= 666) q[i0+2] = ex + s01;
    __syncthreads();

    const int KS[6] = {5, 11, 21, 39, 77, 155};
#pragma unroll
    for (int s = 0; s < 6; ++s){
        int K = KS[s], P = K >> 1;
        for (int x = tid; x < 512; x += 256){
            int lo = x + 77 - P;
            d_S[(size_t)s*NPIX + base + x] = q[lo + K] - q[lo];
        }
    }
}

// ---- hpass: 4 rows x 512 cols per block; thread = 4 cols x 4 rows ----
template<int K>
__device__ __forceinline__ void hpass_core(int s, int img, char* smraw)
{
    constexpr int P   = K/2;
    constexpr int SH  = ((K + 6)/4)*4;
    constexpr int TS  = 508 + SH;
    constexpr int TSP = (TS + TS/8 + 3) & ~1;
    ulonglong2* tile = (ulonglong2*)smraw;
    ulonglong2* wgu  = (ulonglong2*)(smraw + (size_t)TSP*16);

    const int tx = threadIdx.x;
    const int r0 = blockIdx.x*4;
    const size_t base = ((size_t)img*HNUM + r0)*WNUM;
    const float* src = d_diff + base;
    const float* gwp = d_gw + s*WSTRIDE;
    const float* uwp = d_uw + s*WSTRIDE;

    for (int u = tx; u < TS; u += 128){
        int c = refl(u - P);
        float v0 = src[c], v1 = src[c+WNUM], v2 = src[c+2*WNUM], v3 = src[c+3*WNUM];
        tile[u + (u>>3)] = make_ulonglong2(pk(v0,v1), pk(v2,v3));
    }
    for (int t = tx; t < SH; t += 128){
        float g = gwp[t], u_ = uwp[t];
        wgu[t] = make_ulonglong2(pk(g,g), pk(u_,u_));
    }
    __syncthreads();

    ull aG01[4], aG23[4], aU01[4], aU23[4], wgg[4], wuu[4];
#pragma unroll
    for (int r = 0; r < 4; ++r){
        aG01[r]=0; aG23[r]=0; aU01[r]=0; aU23[r]=0; wgg[r]=0; wuu[r]=0;
    }

    const int w0 = tx*4;
    for (int t0 = 0; t0 < SH; t0 += 4){
#pragma unroll
        for (int j = 0; j < 4; ++j){
            int t = t0 + j;
            ulonglong2 w = wgu[t];
            wgg[j] = w.x; wuu[j] = w.y;
            int u = w0 + t;
            ulonglong2 v = tile[u + (u>>3)];
#pragma unroll
            for (int r = 0; r < 4; ++r){
                const int sl = (j - r) & 3;
                fma2(aG01[r], wgg[sl], v.x);
                fma2(aG23[r], wgg[sl], v.y);
                fma2(aU01[r], wuu[sl], v.x);
                fma2(aU23[r], wuu[sl], v.y);
            }
        }
    }

    float A0[4],A1[4],A2[4],A3[4],B0[4],B1[4],B2[4],B3[4];
#pragma unroll
    for (int r = 0; r < 4; ++r){
        upk(aG01[r], A0[r], A1[r]); upk(aG23[r], A2[r], A3[r]);
        upk(aU01[r], B0[r], B1[r]); upk(aU23[r], B2[r], B3[r]);
    }
    float* dA = d_A + (size_t)s*NPIX + base + w0;
    float* dB = d_B + (size_t)s*NPIX + base + w0;
    *(float4*)(dA)          = make_float4(A0[0],A0[1],A0[2],A0[3]);
    *(float4*)(dA+WNUM)     = make_float4(A1[0],A1[1],A1[2],A1[3]);
    *(float4*)(dA+2*WNUM)   = make_float4(A2[0],A2[1],A2[2],A2[3]);
    *(float4*)(dA+3*WNUM)   = make_float4(A3[0],A3[1],A3[2],A3[3]);
    *(float4*)(dB)          = make_float4(B0[0],B0[1],B0[2],B0[3]);
    *(float4*)(dB+WNUM)     = make_float4(B1[0],B1[1],B1[2],B1[3]);
    *(float4*)(dB+2*WNUM)   = make_float4(B2[0],B2[1],B2[2],B2[3]);
    *(float4*)(dB+3*WNUM)   = make_float4(B3[0],B3[1],B3[2],B3[3]);
}

__global__ void __launch_bounds__(128, 7) hpass_all()
{
    extern __shared__ char smh[];
    int z = blockIdx.z; int so = z/12; int img = z - so*12;
    switch (so){
        case 0: hpass_core<155>(5, img, smh); break;
        case 1: hpass_core<77 >(4, img, smh); break;
        case 2: hpass_core<39 >(3, img, smh); break;
        case 3: hpass_core<21 >(2, img, smh); break;
        case 4: hpass_core<11 >(1, img, smh); break;
        default:hpass_core<5  >(0, img, smh); break;
    }
}

// ---- vpass: 16 cols x 128 rows per block; thread = 2 cols x 8 rows.
// Phase A: U-conv of d_A; Phase B: G-conv of d_B; Phase S: sliding box.
#define VT_STRIDE 18          // padded tile row stride in floats (kills bank conflicts)
#define VW_OFF    20736       // weights offset in dyn smem (max tile = 288*18*4)

template<int K>
__device__ __forceinline__ void vconv_phase(const float* __restrict__ gsrc,
    const float* __restrict__ wsf, float* __restrict__ tile,
    int h0, int col0, int tid, int tx, int rb, ull (&acc)[8])
{
    constexpr int P  = K/2;
    constexpr int SV = ((K + 14)/8)*8;        // >= K+7, mult 8
    constexpr int TR = 120 + SV;

    for (int i = tid; i < TR*8; i += 128){
        int r = i >> 3, c = i & 7;
        *(ull*)&tile[r*VT_STRIDE + 2*c] =
            *(const ull*)&gsrc[(size_t)refl(h0 + r - P)*WNUM + (col0 + 2*c)];
    }
    __syncthreads();

    ull w2[8];
#pragma unroll
    for (int r = 0; r < 8; ++r) w2[r] = 0;

    for (int t0 = 0; t0 < SV; t0 += 8){
#pragma unroll
        for (int j = 0; j < 8; ++j){
            int t = t0 + j;
            float wv = wsf[t];
            w2[j] = pk(wv, wv);
            ull v = *(const ull*)&tile[(rb + t)*VT_STRIDE + 2*tx];
#pragma unroll
            for (int r = 0; r < 8; ++r)
                fma2(acc[r], w2[(j - r) & 7], v);
        }
    }
    __syncthreads();
}

template<int K>
__device__ __forceinline__ void vpass_core(int s, int img, char* smraw, float wloss)
{
    constexpr int P  = K/2;
    constexpr int SV = ((K + 14)/8)*8;
    constexpr int TR = 120 + SV;
    float* tile = (float*)smraw;
    float* wu   = (float*)(smraw + VW_OFF);
    float* wg   = wu + 176;
    float* wred = wg + 176;

    const int tid = threadIdx.x;
    const int tx = tid & 7, ty = tid >> 3;
    const int rb = ty*8;
    const int col0 = blockIdx.x*16;
    const int h0   = blockIdx.y*128;
    const size_t ibase = (size_t)img*(HNUM*WNUM);
    const float* Ap = d_A + (size_t)s*NPIX + ibase;
    const float* Bp = d_B + (size_t)s*NPIX + ibase;
    const float* Sp = d_S + (size_t)s*NPIX + ibase;

    // stage weights (zero-padded to SV)
    const float* uwp = d_uw + s*WSTRIDE;
    const float* gwp = d_gw + s*WSTRIDE;
    for (int t = tid; t < SV; t += 128){ wu[t] = uwp[t]; wg[t] = gwp[t]; }

    ull accA[8], accB[8];
#pragma unroll
    for (int r = 0; r < 8; ++r){ accA[r]=0; accB[r]=0; }

    vconv_phase<K>(Ap, wu, tile, h0, col0, tid, tx, rb, accA);
    vconv_phase<K>(Bp, wg, tile, h0, col0, tid, tx, rb, accB);

    // Phase S: fill S tile, sliding-box per thread
    for (int i = tid; i < TR*8; i += 128){
        int r = i >> 3, c = i & 7;
        *(ull*)&tile[r*VT_STRIDE + 2*c] =
            *(const ull*)&Sp[(size_t)refl(h0 + r - P)*WNUM + (col0 + 2*c)];
    }
    __syncthreads();

    // init window with 4 independent chains
    ull p0=0, p1=0, p2=0, p3=0;
    {
        int t = 0;
        for (; t + 3 < K; t += 4){
            add2(p0, *(const ull*)&tile[(rb+t  )*VT_STRIDE + 2*tx]);
            add2(p1, *(const ull*)&tile[(rb+t+1)*VT_STRIDE + 2*tx]);
            add2(p2, *(const ull*)&tile[(rb+t+2)*VT_STRIDE + 2*tx]);
            add2(p3, *(const ull*)&tile[(rb+t+3)*VT_STRIDE + 2*tx]);
        }
        for (; t < K; ++t)
            add2(p0, *(const ull*)&tile[(rb+t)*VT_STRIDE + 2*tx]);
    }
    add2(p0, p1); add2(p2, p3); add2(p0, p2);
    ull sbox = p0;

    const float cn = -d_c[s];
    const ull CN2  = pk(cn, cn);
    const ull NEG1 = pk(-1.f, -1.f);
    float ls = 0.f;
#pragma unroll
    for (int r = 0; r < 8; ++r){
        if (r){
            add2(sbox, *(const ull*)&tile[(rb + r - 1 + K)*VT_STRIDE + 2*tx]);
            fma2(sbox, *(const ull*)&tile[(rb + r - 1)*VT_STRIDE + 2*tx], NEG1);
        }
        ull o = accA[r];
        add2(o, accB[r]);
        fma2(o, sbox, CN2);
        float o0, o1;
        upk(o, o0, o1);
        ls += o0*o0 + o1*o1;
    }
#pragma unroll
    for (int off = 16; off; off >>= 1) ls += __shfl_down_sync(0xffffffffu, ls, off);
    if ((tid & 31) == 0) wred[tid >> 5] = ls;
    __syncthreads();
    if (tid == 0){
        float tot = wred[0] + wred[1] + wred[2] + wred[3];
        int slot = (blockIdx.x + blockIdx.y*32 + blockIdx.z*7) & 63;
        atomicAdd(&d_accv[slot], (double)tot * (double)wloss);
    }
}

__global__ void __launch_bounds__(128, 8) vpass_all()
{
    extern __shared__ char smv[];
    int z = blockIdx.z; int so = z/12; int img = z - so*12;
    switch (so){
        case 0: vpass_core<155>(5, img, smv, 10.f);  break;
        case 1: vpass_core<77 >(4, img, smv, 10.f);  break;
        case 2: vpass_core<39 >(3, img, smv, 20.f);  break;
        case 3: vpass_core<21 >(2, img, smv, 400.f); break;
        case 4: vpass_core<11 >(1, img, smv, 500.f); break;
        default:vpass_core<5  >(0, img, smv, 600.f); break;
    }
}

// ---- finalize ----
__global__ void final_kernel(float* out){
    double t = 0.0;
#pragma unroll
    for (int i = 0; i < 64; ++i) t += d_accv[i];
    out[0] = (float)(t * (1.0 / (double)NPIX));
}

extern "C" void kernel_launch(void* const* d_in, const int* in_sizes, int n_in,
                              void* d_out, int out_size)
{
    const float* input  = (const float*)d_in[0];
    const float* target = (const float*)d_in[1];
    float* out = (float*)d_out;

    // hpass dyn smem: TSP*16 + SH*16 (K=155: TSP=754, SH=160) = 14624
    const int HS = 14624;
    // vpass dyn smem: tile 288*18*4 = 20736 + 2*176*4 + 16 = 22160
    const int VS = 22160;

    init_kernel<<<1, 256>>>();
    diff_prefix_kernel<<<dim3(512, NIMG), 256>>>(input, target);
    hpass_all<<<dim3(128, 1, 72), 128, HS>>>();
    vpass_all<<<dim3(32, 4, 72), 128, VS>>>();
    final_kernel<<<1, 1>>>(out);
}

// round 6
// speedup vs baseline: 2.0744x; 1.6907x over previous
#include <cuda_runtime.h>
#include <math.h>

#define HNUM 512
#define WNUM 512
#define NIMG 12
#define NPIX (NIMG*HNUM*WNUM)
#define WSTRIDE 176

typedef unsigned long long ull;

// ---- constant weights (host-computed, packed {w,w}) ----
__constant__ ull   c_g2[6*WSTRIDE];
__constant__ ull   c_u2[6*WSTRIDE];
__constant__ ull   c_cn2[6];          // packed {-c,-c}

// ---- scratch ----
__device__ float  d_diff[NPIX];
__device__ float  d_A[(size_t)6*NPIX];
__device__ float  d_B[(size_t)6*NPIX];
__device__ float  d_S[(size_t)6*NPIX];
__device__ double d_accv[64];

__device__ __forceinline__ int refl(int t){
    int r = t < 0 ? -t : t;
    return r >= HNUM ? (2*HNUM - 2 - r) : r;
}
__device__ __forceinline__ ull pk(float x, float y){
    ull r; asm("mov.b64 %0,{%1,%2};" : "=l"(r) : "f"(x), "f"(y)); return r;
}
__device__ __forceinline__ void upk(ull v, float& x, float& y){
    asm("mov.b64 {%0,%1},%2;" : "=f"(x), "=f"(y) : "l"(v));
}
__device__ __forceinline__ void fma2(ull& d, ull a, ull b){
    asm("fma.rn.f32x2 %0,%1,%2,%0;" : "+l"(d) : "l"(a), "l"(b));
}
__device__ __forceinline__ void add2(ull& d, ull a){
    asm("add.rn.f32x2 %0,%0,%1;" : "+l"(d) : "l"(a));
}
__device__ __forceinline__ void cpa8(void* s, const void* g){
    unsigned sa = (unsigned)__cvta_generic_to_shared(s);
    asm volatile("cp.async.ca.shared.global [%0], [%1], 8;" :: "r"(sa), "l"(g));
}
__device__ __forceinline__ void cpa_wait(){
    asm volatile("cp.async.commit_group;");
    asm volatile("cp.async.wait_group 0;" ::: "memory");
}

__global__ void zero_acc(){ d_accv[threadIdx.x] = 0.0; }

// ---- fused diff + per-row prefix + box-along-W for all sigmas ----
__global__ void __launch_bounds__(256) diff_prefix_kernel(
    const float* __restrict__ in, const float* __restrict__ tg)
{
    __shared__ float dr[512];
    __shared__ float q[667];
    __shared__ float wsum[8];

    const int row = blockIdx.x, img = blockIdx.y;
    const size_t base = ((size_t)img*HNUM + row)*WNUM;
    const int tid = threadIdx.x;

    for (int x = tid; x < 512; x += 256){
        float d = in[base+x] - tg[base+x];
        dr[x] = d;
        d_diff[base+x] = d;
    }
    __syncthreads();

    const int i0 = tid*3;
    float v0 = (i0   < 666) ? dr[refl(i0-77)] : 0.f;
    float v1 = (i0+1 < 666) ? dr[refl(i0-76)] : 0.f;
    float v2 = (i0+2 < 666) ? dr[refl(i0-75)] : 0.f;
    float s01 = v0 + v1;
    float tot = s01 + v2;

    float inc = tot;
#pragma unroll
    for (int off = 1; off < 32; off <<= 1){
        float n = __shfl_up_sync(0xffffffffu, inc, off);
        if ((tid & 31) >= off) inc += n;
    }
    if ((tid & 31) == 31) wsum[tid >> 5] = inc;
    __syncthreads();
    if (tid == 0){
        float a = 0.f;
#pragma unroll
        for (int i = 0; i < 8; ++i){ float t = wsum[i]; wsum[i] = a; a += t; }
    }
    __syncthreads();
    float ex = inc - tot + wsum[tid >> 5];
    if (i0   <= 666) q[i0]   = ex;
    if (i0+1 <= 666) q[i0+1] = ex + v0;
    if (i0+2 <= 666) q[i0+2] = ex + s01;
    __syncthreads();

    const int KS[6] = {5, 11, 21, 39, 77, 155};
#pragma unroll
    for (int s = 0; s < 6; ++s){
        int K = KS[s], P = K >> 1;
        for (int x = tid; x < 512; x += 256){
            int lo = x + 77 - P;
            d_S[(size_t)s*NPIX + base + x] = q[lo + K] - q[lo];
        }
    }
}

// ---- hpass: 4 rows x 512 cols per block; thread = 4 cols x 4 rows ----
template<int K>
__device__ __forceinline__ void hpass_core(int s, int img, char* smraw)
{
    constexpr int P   = K/2;
    constexpr int SH  = ((K + 6)/4)*4;
    constexpr int TS  = 508 + SH;
    ulonglong2* tile = (ulonglong2*)smraw;
    const int sbase = s*WSTRIDE;

    const int tx = threadIdx.x;
    const int r0 = blockIdx.x*4;
    const size_t base = ((size_t)img*HNUM + r0)*WNUM;
    const float* src = d_diff + base;

    for (int u = tx; u < TS; u += 128){
        int c = refl(u - P);
        float v0 = src[c], v1 = src[c+WNUM], v2 = src[c+2*WNUM], v3 = src[c+3*WNUM];
        tile[u + (u>>3)] = make_ulonglong2(pk(v0,v1), pk(v2,v3));
    }
    __syncthreads();

    ull aG01[4], aG23[4], aU01[4], aU23[4], wgg[4], wuu[4];
#pragma unroll
    for (int r = 0; r < 4; ++r){
        aG01[r]=0; aG23[r]=0; aU01[r]=0; aU23[r]=0; wgg[r]=0; wuu[r]=0;
    }

    const int w0 = tx*4;
    for (int t0 = 0; t0 < SH; t0 += 4){
#pragma unroll
        for (int j = 0; j < 4; ++j){
            int t = t0 + j;
            wgg[j] = c_g2[sbase + t];
            wuu[j] = c_u2[sbase + t];
            int u = w0 + t;
            ulonglong2 v = tile[u + (u>>3)];
#pragma unroll
            for (int r = 0; r < 4; ++r){
                const int sl = (j - r) & 3;
                fma2(aG01[r], wgg[sl], v.x);
                fma2(aG23[r], wgg[sl], v.y);
                fma2(aU01[r], wuu[sl], v.x);
                fma2(aU23[r], wuu[sl], v.y);
            }
        }
    }

    float A0[4],A1[4],A2[4],A3[4],B0[4],B1[4],B2[4],B3[4];
#pragma unroll
    for (int r = 0; r < 4; ++r){
        upk(aG01[r], A0[r], A1[r]); upk(aG23[r], A2[r], A3[r]);
        upk(aU01[r], B0[r], B1[r]); upk(aU23[r], B2[r], B3[r]);
    }
    float* dA = d_A + (size_t)s*NPIX + base + w0;
    float* dB = d_B + (size_t)s*NPIX + base + w0;
    *(float4*)(dA)          = make_float4(A0[0],A0[1],A0[2],A0[3]);
    *(float4*)(dA+WNUM)     = make_float4(A1[0],A1[1],A1[2],A1[3]);
    *(float4*)(dA+2*WNUM)   = make_float4(A2[0],A2[1],A2[2],A2[3]);
    *(float4*)(dA+3*WNUM)   = make_float4(A3[0],A3[1],A3[2],A3[3]);
    *(float4*)(dB)          = make_float4(B0[0],B0[1],B0[2],B0[3]);
    *(float4*)(dB+WNUM)     = make_float4(B1[0],B1[1],B1[2],B1[3]);
    *(float4*)(dB+2*WNUM)   = make_float4(B2[0],B2[1],B2[2],B2[3]);
    *(float4*)(dB+3*WNUM)   = make_float4(B3[0],B3[1],B3[2],B3[3]);
}

__global__ void __launch_bounds__(128, 8) hpass_all()
{
    extern __shared__ char smh[];
    int z = blockIdx.z; int so = z/12; int img = z - so*12;
    switch (so){
        case 0: hpass_core<155>(5, img, smh); break;
        case 1: hpass_core<77 >(4, img, smh); break;
        case 2: hpass_core<39 >(3, img, smh); break;
        case 3: hpass_core<21 >(2, img, smh); break;
        case 4: hpass_core<11 >(1, img, smh); break;
        default:hpass_core<5  >(0, img, smh); break;
    }
}

// ---- vpass: 16 cols x 128 rows per block; thread = 2 cols x 8 rows ----
#define VT_STRIDE 18
#define V_ROFF    20736
#define V_WRED    21888

template<int K, int WSEL>
__device__ __forceinline__ void vconv_phase(const float* __restrict__ gsrc,
    int sbase, float* __restrict__ tile, int* __restrict__ rowoff,
    int h0, int col0, int tid, int tx, int rb, ull (&acc)[8], bool first)
{
    constexpr int P  = K/2;
    constexpr int SV = ((K + 14)/8)*8;
    constexpr int TR = 120 + SV;

    if (first){
        for (int i = tid; i < TR*8; i += 128){
            int r = i >> 3, c = i & 7;
            int ro = refl(h0 + r - P)*WNUM;
            if (c == 0) rowoff[r] = ro;
            cpa8(&tile[r*VT_STRIDE + 2*c], gsrc + ro + col0 + 2*c);
        }
    } else {
        for (int i = tid; i < TR*8; i += 128){
            int r = i >> 3, c = i & 7;
            cpa8(&tile[r*VT_STRIDE + 2*c], gsrc + rowoff[r] + col0 + 2*c);
        }
    }
    cpa_wait();
    __syncthreads();

    ull w2[8];
#pragma unroll
    for (int r = 0; r < 8; ++r) w2[r] = 0;

    for (int t0 = 0; t0 < SV; t0 += 8){
#pragma unroll
        for (int j = 0; j < 8; ++j){
            int t = t0 + j;
            w2[j] = WSEL ? c_g2[sbase + t] : c_u2[sbase + t];
            ull v = *(const ull*)&tile[(rb + t)*VT_STRIDE + 2*tx];
#pragma unroll
            for (int r = 0; r < 8; ++r)
                fma2(acc[r], w2[(j - r) & 7], v);
        }
    }
    __syncthreads();
}

template<int K>
__device__ __forceinline__ void vpass_core(int s, int img, char* smraw, float wloss)
{
    constexpr int P  = K/2;
    constexpr int SV = ((K + 14)/8)*8;
    constexpr int TR = 120 + SV;
    float* tile   = (float*)smraw;
    int*   rowoff = (int*)(smraw + V_ROFF);
    float* wred   = (float*)(smraw + V_WRED);
    const int sbase = s*WSTRIDE;

    const int tid = threadIdx.x;
    const int tx = tid & 7, ty = tid >> 3;
    const int rb = ty*8;
    const int col0 = blockIdx.x*16;
    const int h0   = blockIdx.y*128;
    const size_t ibase = (size_t)img*(HNUM*WNUM);
    const float* Ap = d_A + (size_t)s*NPIX + ibase;
    const float* Bp = d_B + (size_t)s*NPIX + ibase;
    const float* Sp = d_S + (size_t)s*NPIX + ibase;

    ull accA[8], accB[8];
#pragma unroll
    for (int r = 0; r < 8; ++r){ accA[r]=0; accB[r]=0; }

    vconv_phase<K,0>(Ap, sbase, tile, rowoff, h0, col0, tid, tx, rb, accA, true);
    vconv_phase<K,1>(Bp, sbase, tile, rowoff, h0, col0, tid, tx, rb, accB, false);

    // Phase S: fill tile, sliding-box per thread
    for (int i = tid; i < TR*8; i += 128){
        int r = i >> 3, c = i & 7;
        cpa8(&tile[r*VT_STRIDE + 2*c], Sp + rowoff[r] + col0 + 2*c);
    }
    cpa_wait();
    __syncthreads();

    // init window with 4 independent chains
    ull p0=0, p1=0, p2=0, p3=0;
    {
        int t = 0;
        for (; t + 3 < K; t += 4){
            add2(p0, *(const ull*)&tile[(rb+t  )*VT_STRIDE + 2*tx]);
            add2(p1, *(const ull*)&tile[(rb+t+1)*VT_STRIDE + 2*tx]);
            add2(p2, *(const ull*)&tile[(rb+t+2)*VT_STRIDE + 2*tx]);
            add2(p3, *(const ull*)&tile[(rb+t+3)*VT_STRIDE + 2*tx]);
        }
        for (; t < K; ++t)
            add2(p0, *(const ull*)&tile[(rb+t)*VT_STRIDE + 2*tx]);
    }
    add2(p0, p1); add2(p2, p3); add2(p0, p2);
    ull sbox = p0;

    const ull CN2  = c_cn2[s];
    const ull NEG1 = pk(-1.f, -1.f);
    float ls = 0.f;
#pragma unroll
    for (int r = 0; r < 8; ++r){
        if (r){
            add2(sbox, *(const ull*)&tile[(rb + r - 1 + K)*VT_STRIDE + 2*tx]);
            fma2(sbox, *(const ull*)&tile[(rb + r - 1)*VT_STRIDE + 2*tx], NEG1);
        }
        ull o = accA[r];
        add2(o, accB[r]);
        fma2(o, sbox, CN2);
        float o0, o1;
        upk(o, o0, o1);
        ls += o0*o0 + o1*o1;
    }
#pragma unroll
    for (int off = 16; off; off >>= 1) ls += __shfl_down_sync(0xffffffffu, ls, off);
    if ((tid & 31) == 0) wred[tid >> 5] = ls;
    __syncthreads();
    if (tid == 0){
        float tot = wred[0] + wred[1] + wred[2] + wred[3];
        int slot = (blockIdx.x + blockIdx.y*32 + blockIdx.z*7) & 63;
        atomicAdd(&d_accv[slot], (double)tot * (double)wloss);
    }
}

__global__ void __launch_bounds__(128, 8) vpass_all()
{
    extern __shared__ char smv[];
    int z = blockIdx.z; int so = z/12; int img = z - so*12;
    switch (so){
        case 0: vpass_core<155>(5, img, smv, 10.f);  break;
        case 1: vpass_core<77 >(4, img, smv, 10.f);  break;
        case 2: vpass_core<39 >(3, img, smv, 20.f);  break;
        case 3: vpass_core<21 >(2, img, smv, 400.f); break;
        case 4: vpass_core<11 >(1, img, smv, 500.f); break;
        default:vpass_core<5  >(0, img, smv, 600.f); break;
    }
}

// ---- finalize ----
__global__ void final_kernel(float* out){
    double t = 0.0;
#pragma unroll
    for (int i = 0; i < 64; ++i) t += d_accv[i];
    out[0] = (float)(t * (1.0 / (double)NPIX));
}

// ---- host-side weight build ----
static ull  h_g2[6*WSTRIDE];
static ull  h_u2[6*WSTRIDE];
static ull  h_cn2[6];

static inline ull hpack2(float x){
    unsigned u; __builtin_memcpy(&u, &x, 4);
    return (ull)u | ((ull)u << 32);
}

static void build_weights(){
    const double sig[6] = {0.6, 1.2, 2.4, 4.8, 9.6, 19.2};
    const int    ks [6] = {5, 11, 21, 39, 77, 155};
    for (int s = 0; s < 6; ++s){
        int K = ks[s], half = K/2;
        double ss = sig[s]*sig[s];
        double sn = 0.3989422804014327 / ss;
        double sg = 0.0, su = 0.0;
        for (int j = 0; j < WSTRIDE; ++j){
            float g = 0.f, u = 0.f;
            if (j < K){
                double t  = (double)(j - half);
                double t2 = t*t;
                double e  = exp(-t2 / (2.0*ss));
                g = (float)(e * sn);
                u = (float)((t2 - ss) * e * sn);
                sg += (double)g; su += (double)u;
            }
            h_g2[s*WSTRIDE + j] = hpack2(g);
            h_u2[s*WSTRIDE + j] = hpack2(u);
        }
        float cn = -(float)(2.0 * sg * su / ((double)K * (double)K));
        h_cn2[s] = hpack2(cn);
    }
}

extern "C" void kernel_launch(void* const* d_in, const int* in_sizes, int n_in,
                              void* d_out, int out_size)
{
    const float* input  = (const float*)d_in[0];
    const float* target = (const float*)d_in[1];
    float* out = (float*)d_out;

    build_weights();
    cudaMemcpyToSymbolAsync(c_g2,  h_g2,  sizeof(h_g2),  0, cudaMemcpyHostToDevice, 0);
    cudaMemcpyToSymbolAsync(c_u2,  h_u2,  sizeof(h_u2),  0, cudaMemcpyHostToDevice, 0);
    cudaMemcpyToSymbolAsync(c_cn2, h_cn2, sizeof(h_cn2), 0, cudaMemcpyHostToDevice, 0);

    const int HS = 12064;   // hpass: TSP*16 for K=155 (TSP=754)
    const int VS = 21920;   // vpass: tile 20736 + rowoff 1152 + wred

    zero_acc<<<1, 64>>>();
    diff_prefix_kernel<<<dim3(512, NIMG), 256>>>(input, target);
    hpass_all<<<dim3(128, 1, 72), 128, HS>>>();
    vpass_all<<<dim3(32, 4, 72), 128, VS>>>();
    final_kernel<<<1, 1>>>(out);
}

// round 7
// speedup vs baseline: 2.0829x; 1.0041x over previous
#include <cuda_runtime.h>
#include <math.h>

#define HNUM 512
#define WNUM 512
#define NIMG 12
#define NPIX (NIMG*HNUM*WNUM)
#define WSTRIDE 176

typedef unsigned long long ull;

// ---- constant weights (host-computed) ----
__constant__ ull   c_g2[6*WSTRIDE];    // {g,g}  (hpass)
__constant__ ull   c_u2[6*WSTRIDE];    // {u,u}  (hpass)
__constant__ ull   c_ug2[6*WSTRIDE];   // {u,g}  (vpass stream-packed)
__constant__ float c_cn[6];            // -c

// ---- scratch ----
__device__ float  d_diff[NPIX];
__device__ ull    d_AB[(size_t)6*NPIX];   // per-sigma interleaved {A,B}
__device__ float  d_S[(size_t)6*NPIX];
__device__ double d_accv[64];

__device__ __forceinline__ int refl(int t){
    int r = t < 0 ? -t : t;
    return r >= HNUM ? (2*HNUM - 2 - r) : r;
}
__device__ __forceinline__ ull pk(float x, float y){
    ull r; asm("mov.b64 %0,{%1,%2};" : "=l"(r) : "f"(x), "f"(y)); return r;
}
__device__ __forceinline__ void upk(ull v, float& x, float& y){
    asm("mov.b64 {%0,%1},%2;" : "=f"(x), "=f"(y) : "l"(v));
}
__device__ __forceinline__ void fma2(ull& d, ull a, ull b){
    asm("fma.rn.f32x2 %0,%1,%2,%0;" : "+l"(d) : "l"(a), "l"(b));
}
__device__ __forceinline__ void add2(ull& d, ull a){
    asm("add.rn.f32x2 %0,%0,%1;" : "+l"(d) : "l"(a));
}
__device__ __forceinline__ void cpa8(void* s, const void* g){
    unsigned sa = (unsigned)__cvta_generic_to_shared(s);
    asm volatile("cp.async.ca.shared.global [%0], [%1], 8;" :: "r"(sa), "l"(g));
}
__device__ __forceinline__ void cpa16(void* s, const void* g){
    unsigned sa = (unsigned)__cvta_generic_to_shared(s);
    asm volatile("cp.async.cg.shared.global [%0], [%1], 16;" :: "r"(sa), "l"(g));
}
__device__ __forceinline__ void cpa_wait(){
    asm volatile("cp.async.commit_group;");
    asm volatile("cp.async.wait_group 0;" ::: "memory");
}

__global__ void zero_acc(){ d_accv[threadIdx.x] = 0.0; }

// ---- fused diff + per-row prefix + box-along-W for all sigmas ----
__global__ void __launch_bounds__(256) diff_prefix_kernel(
    const float* __restrict__ in, const float* __restrict__ tg)
{
    __shared__ float dr[512];
    __shared__ float q[667];
    __shared__ float wsum[8];

    const int row = blockIdx.x, img = blockIdx.y;
    const size_t base = ((size_t)img*HNUM + row)*WNUM;
    const int tid = threadIdx.x;

    for (int x = tid; x < 512; x += 256){
        float d = in[base+x] - tg[base+x];
        dr[x] = d;
        d_diff[base+x] = d;
    }
    __syncthreads();

    const int i0 = tid*3;
    float v0 = (i0   < 666) ? dr[refl(i0-77)] : 0.f;
    float v1 = (i0+1 < 666) ? dr[refl(i0-76)] : 0.f;
    float v2 = (i0+2 < 666) ? dr[refl(i0-75)] : 0.f;
    float s01 = v0 + v1;
    float tot = s01 + v2;

    float inc = tot;
#pragma unroll
    for (int off = 1; off < 32; off <<= 1){
        float n = __shfl_up_sync(0xffffffffu, inc, off);
        if ((tid & 31) >= off) inc += n;
    }
    if ((tid & 31) == 31) wsum[tid >> 5] = inc;
    __syncthreads();
    if (tid == 0){
        float a = 0.f;
#pragma unroll
        for (int i = 0; i < 8; ++i){ float t = wsum[i]; wsum[i] = a; a += t; }
    }
    __syncthreads();
    float ex = inc - tot + wsum[tid >> 5];
    if (i0   <= 666) q[i0]   = ex;
    if (i0+1 <= 666) q[i0+1] = ex + v0;
    if (i0+2 <= 666) q[i0+2] = ex + s01;
    __syncthreads();

    const int KS[6] = {5, 11, 21, 39, 77, 155};
#pragma unroll
    for (int s = 0; s < 6; ++s){
        int K = KS[s], P = K >> 1;
        for (int x = tid; x < 512; x += 256){
            int lo = x + 77 - P;
            d_S[(size_t)s*NPIX + base + x] = q[lo + K] - q[lo];
        }
    }
}

// ---- hpass: 4 rows x 512 cols per block; thread = 4 cols x 4 rows ----
template<int K>
__device__ __forceinline__ void hpass_core(int s, int img, char* smraw)
{
    constexpr int P   = K/2;
    constexpr int SH  = ((K + 6)/4)*4;
    constexpr int TS  = 508 + SH;
    ulonglong2* tile = (ulonglong2*)smraw;
    const int sbase = s*WSTRIDE;

    const int tx = threadIdx.x;
    const int r0 = blockIdx.x*4;
    const size_t base = ((size_t)img*HNUM + r0)*WNUM;
    const float* src = d_diff + base;

    for (int u = tx; u < TS; u += 128){
        int c = refl(u - P);
        float v0 = src[c], v1 = src[c+WNUM], v2 = src[c+2*WNUM], v3 = src[c+3*WNUM];
        tile[u + (u>>3)] = make_ulonglong2(pk(v0,v1), pk(v2,v3));
    }
    __syncthreads();

    ull aG01[4], aG23[4], aU01[4], aU23[4], wgg[4], wuu[4];
#pragma unroll
    for (int r = 0; r < 4; ++r){
        aG01[r]=0; aG23[r]=0; aU01[r]=0; aU23[r]=0; wgg[r]=0; wuu[r]=0;
    }

    const int w0 = tx*4;
    for (int t0 = 0; t0 < SH; t0 += 4){
#pragma unroll
        for (int j = 0; j < 4; ++j){
            int t = t0 + j;
            wgg[j] = c_g2[sbase + t];
            wuu[j] = c_u2[sbase + t];
            int u = w0 + t;
            ulonglong2 v = tile[u + (u>>3)];
#pragma unroll
            for (int r = 0; r < 4; ++r){
                const int sl = (j - r) & 3;
                fma2(aG01[r], wgg[sl], v.x);
                fma2(aG23[r], wgg[sl], v.y);
                fma2(aU01[r], wuu[sl], v.x);
                fma2(aU23[r], wuu[sl], v.y);
            }
        }
    }

    float A0[4],A1[4],A2[4],A3[4],B0[4],B1[4],B2[4],B3[4];
#pragma unroll
    for (int r = 0; r < 4; ++r){
        upk(aG01[r], A0[r], A1[r]); upk(aG23[r], A2[r], A3[r]);
        upk(aU01[r], B0[r], B1[r]); upk(aU23[r], B2[r], B3[r]);
    }
    ull* dst = d_AB + (size_t)s*NPIX + base + w0;
    *(ulonglong2*)(dst)          = make_ulonglong2(pk(A0[0],B0[0]), pk(A0[1],B0[1]));
    *(ulonglong2*)(dst+2)        = make_ulonglong2(pk(A0[2],B0[2]), pk(A0[3],B0[3]));
    *(ulonglong2*)(dst+WNUM)     = make_ulonglong2(pk(A1[0],B1[0]), pk(A1[1],B1[1]));
    *(ulonglong2*)(dst+WNUM+2)   = make_ulonglong2(pk(A1[2],B1[2]), pk(A1[3],B1[3]));
    *(ulonglong2*)(dst+2*WNUM)   = make_ulonglong2(pk(A2[0],B2[0]), pk(A2[1],B2[1]));
    *(ulonglong2*)(dst+2*WNUM+2) = make_ulonglong2(pk(A2[2],B2[2]), pk(A2[3],B2[3]));
    *(ulonglong2*)(dst+3*WNUM)   = make_ulonglong2(pk(A3[0],B3[0]), pk(A3[1],B3[1]));
    *(ulonglong2*)(dst+3*WNUM+2) = make_ulonglong2(pk(A3[2],B3[2]), pk(A3[3],B3[3]));
}

__global__ void __launch_bounds__(128, 8) hpass_all()
{
    extern __shared__ char smh[];
    int z = blockIdx.z; int so = z/12; int img = z - so*12;
    switch (so){
        case 0: hpass_core<155>(5, img, smh); break;
        case 1: hpass_core<77 >(4, img, smh); break;
        case 2: hpass_core<39 >(3, img, smh); break;
        case 3: hpass_core<21 >(2, img, smh); break;
        case 4: hpass_core<11 >(1, img, smh); break;
        default:hpass_core<5  >(0, img, smh); break;
    }
}

// ---- vpass: 16 cols x 128 rows per block; thread = 2 cols x 8 rows ----
// Phase AB: stream-packed conv {u*A, g*B} on swizzled interleaved tile.
// Phase S: sliding box.
#define VAB_BYTES 36864     // max AB tile: 288 rows * 16 ull

template<int K>
__device__ __forceinline__ void vpass_core(int s, int img, char* smraw, float wloss)
{
    constexpr int P  = K/2;
    constexpr int SV = ((K + 14)/8)*8;
    constexpr int TR = 120 + SV;
    ull*   tileAB = (ull*)smraw;                 // [TR][16] swizzled pair-slots
    float* tileS  = (float*)smraw;               // reuse: [TR][18]
    float* wred   = (float*)(smraw + VAB_BYTES);
    const int sbase = s*WSTRIDE;

    const int tid = threadIdx.x;
    const int tx = tid & 7, ty = tid >> 3;
    const int rb = ty*8;
    const int col0 = blockIdx.x*16;
    const int h0   = blockIdx.y*128;
    const size_t ibase = (size_t)img*(HNUM*WNUM);
    const ull*   ABp = d_AB + (size_t)s*NPIX + ibase;
    const float* Sp  = d_S  + (size_t)s*NPIX + ibase;

    // fill AB tile with pair-slot swizzle: slot = (p + (r>>3)) & 7
    for (int i = tid; i < TR*8; i += 128){
        int r = i >> 3, p = i & 7;
        int ro = refl(h0 + r - P)*WNUM;
        int sl = (p + (r >> 3)) & 7;
        cpa16(&tileAB[r*16 + sl*2], ABp + ro + col0 + 2*p);
    }
    cpa_wait();
    __syncthreads();

    ull accX[8], accY[8], w2[8];
#pragma unroll
    for (int r = 0; r < 8; ++r){ accX[r]=0; accY[r]=0; w2[r]=0; }

    for (int t0 = 0; t0 < SV; t0 += 8){
        // rb + t0 is a multiple of 8 -> swizzle slot constant across the 8 j's
        const ull* trow = &tileAB[(rb + t0)*16 + (((tx + ((rb + t0) >> 3)) & 7) << 1)];
#pragma unroll
        for (int j = 0; j < 8; ++j){
            w2[j] = c_ug2[sbase + t0 + j];
            ulonglong2 v = *(const ulonglong2*)(trow + j*16);
#pragma unroll
            for (int r = 0; r < 8; ++r){
                const int sl = (j - r) & 7;
                fma2(accX[r], w2[sl], v.x);
                fma2(accY[r], w2[sl], v.y);
            }
        }
    }
    __syncthreads();

    // Phase S: fill (stride-18 float rows), sliding box
    for (int i = tid; i < TR*8; i += 128){
        int r = i >> 3, c = i & 7;
        int ro = refl(h0 + r - P)*WNUM;
        cpa8(&tileS[r*18 + 2*c], Sp + ro + col0 + 2*c);
    }
    cpa_wait();
    __syncthreads();

    ull p0=0, p1=0, p2=0, p3=0;
    {
        int t = 0;
        for (; t + 3 < K; t += 4){
            add2(p0, *(const ull*)&tileS[(rb+t  )*18 + 2*tx]);
            add2(p1, *(const ull*)&tileS[(rb+t+1)*18 + 2*tx]);
            add2(p2, *(const ull*)&tileS[(rb+t+2)*18 + 2*tx]);
            add2(p3, *(const ull*)&tileS[(rb+t+3)*18 + 2*tx]);
        }
        for (; t < K; ++t)
            add2(p0, *(const ull*)&tileS[(rb+t)*18 + 2*tx]);
    }
    add2(p0, p1); add2(p2, p3); add2(p0, p2);
    ull sbox = p0;

    const float cn = c_cn[s];
    const ull NEG1 = pk(-1.f, -1.f);
    float ls = 0.f;
#pragma unroll
    for (int r = 0; r < 8; ++r){
        if (r){
            add2(sbox, *(const ull*)&tileS[(rb + r - 1 + K)*18 + 2*tx]);
            fma2(sbox, *(const ull*)&tileS[(rb + r - 1)*18 + 2*tx], NEG1);
        }
        float xa, xb, ya, yb, s0, s1;
        upk(accX[r], xa, xb);     // col 2tx:   {u*A, g*B} partials
        upk(accY[r], ya, yb);     // col 2tx+1
        upk(sbox, s0, s1);
        float o0 = fmaf(cn, s0, xa + xb);
        float o1 = fmaf(cn, s1, ya + yb);
        ls += o0*o0 + o1*o1;
    }
#pragma unroll
    for (int off = 16; off; off >>= 1) ls += __shfl_down_sync(0xffffffffu, ls, off);
    if ((tid & 31) == 0) wred[tid >> 5] = ls;
    __syncthreads();
    if (tid == 0){
        float tot = wred[0] + wred[1] + wred[2] + wred[3];
        int slot = (blockIdx.x + blockIdx.y*32 + blockIdx.z*7) & 63;
        atomicAdd(&d_accv[slot], (double)tot * (double)wloss);
    }
}

__global__ void __launch_bounds__(128, 6) vpass_all()
{
    extern __shared__ char smv[];
    int z = blockIdx.z; int so = z/12; int img = z - so*12;
    switch (so){
        case 0: vpass_core<155>(5, img, smv, 10.f);  break;
        case 1: vpass_core<77 >(4, img, smv, 10.f);  break;
        case 2: vpass_core<39 >(3, img, smv, 20.f);  break;
        case 3: vpass_core<21 >(2, img, smv, 400.f); break;
        case 4: vpass_core<11 >(1, img, smv, 500.f); break;
        default:vpass_core<5  >(0, img, smv, 600.f); break;
    }
}

// ---- finalize ----
__global__ void final_kernel(float* out){
    double t = 0.0;
#pragma unroll
    for (int i = 0; i < 64; ++i) t += d_accv[i];
    out[0] = (float)(t * (1.0 / (double)NPIX));
}

// ---- host-side weight build ----
static ull   h_g2[6*WSTRIDE];
static ull   h_u2[6*WSTRIDE];
static ull   h_ug2[6*WSTRIDE];
static float h_cn[6];

static inline ull hpack(float x, float y){
    unsigned a, b; __builtin_memcpy(&a, &x, 4); __builtin_memcpy(&b, &y, 4);
    return (ull)a | ((ull)b << 32);
}

static void build_weights(){
    const double sig[6] = {0.6, 1.2, 2.4, 4.8, 9.6, 19.2};
    const int    ks [6] = {5, 11, 21, 39, 77, 155};
    for (int s = 0; s < 6; ++s){
        int K = ks[s], half = K/2;
        double ss = sig[s]*sig[s];
        double sn = 0.3989422804014327 / ss;
        double sg = 0.0, su = 0.0;
        for (int j = 0; j < WSTRIDE; ++j){
            float g = 0.f, u = 0.f;
            if (j < K){
                double t  = (double)(j - half);
                double t2 = t*t;
                double e  = exp(-t2 / (2.0*ss));
                g = (float)(e * sn);
                u = (float)((t2 - ss) * e * sn);
                sg += (double)g; su += (double)u;
            }
            h_g2[s*WSTRIDE + j]  = hpack(g, g);
            h_u2[s*WSTRIDE + j]  = hpack(u, u);
            h_ug2[s*WSTRIDE + j] = hpack(u, g);
        }
        h_cn[s] = -(float)(2.0 * sg * su / ((double)K * (double)K));
    }
}

extern "C" void kernel_launch(void* const* d_in, const int* in_sizes, int n_in,
                              void* d_out, int out_size)
{
    const float* input  = (const float*)d_in[0];
    const float* target = (const float*)d_in[1];
    float* out = (float*)d_out;

    build_weights();
    cudaMemcpyToSymbolAsync(c_g2,  h_g2,  sizeof(h_g2),  0, cudaMemcpyHostToDevice, 0);
    cudaMemcpyToSymbolAsync(c_u2,  h_u2,  sizeof(h_u2),  0, cudaMemcpyHostToDevice, 0);
    cudaMemcpyToSymbolAsync(c_ug2, h_ug2, sizeof(h_ug2), 0, cudaMemcpyHostToDevice, 0);
    cudaMemcpyToSymbolAsync(c_cn,  h_cn,  sizeof(h_cn),  0, cudaMemcpyHostToDevice, 0);

    const int HS = 12064;             // hpass tile (K=155: TSP=754 * 16)
    const int VS = VAB_BYTES + 64;    // vpass AB tile + wred

    zero_acc<<<1, 64>>>();
    diff_prefix_kernel<<<dim3(512, NIMG), 256>>>(input, target);
    hpass_all<<<dim3(128, 1, 72), 128, HS>>>();
    vpass_all<<<dim3(32, 4, 72), 128, VS>>>();
    final_kernel<<<1, 1>>>(out);
}